// round 14
// baseline (speedup 1.0000x reference)
#include <cuda_runtime.h>
#include <cuda_fp16.h>
#include <cstdint>
#include <cstddef>

#define BS 8
#define CI 256
#define CO 256
#define HH 128
#define WW 128
#define EPSV 1e-6f

#define CKN 16                    // ci chunks of 16
// Stage layout (halves):
//  X: [xrow 4][chalf 2][pix 130][8 halves] = 8320 halves (16640 B)
//  W: [tap 5][khalf 2][co 128][8 halves]   = 10240 halves (20480 B)
#define XROWH 2080                // one xrow: 2 planes x 130 x 8
#define XPLANEB 2080              // one chalf plane in BYTES: 130*16
#define XH (4 * XROWH)            // 8320
#define WH 10240
#define STAGEH (XH + WH)          // 18560 halves = 37120 B
#define NSTAGE 5
#define TXBYTES (STAGEH * 2)
#define SMEM_DYN (NSTAGE * STAGEH * 2 + 256)

// ---------------- device scratch (no cudaMalloc allowed) ----------------
__device__ __align__(16) __half g_xt[(size_t)BS * CKN * HH * XROWH];
__device__ __align__(16) __half g_weff[(size_t)BS * 2 * CKN * WH];
__device__ float g_demod[BS * CO];
__device__ __align__(16) __half g_zero[XROWH];   // zero halo row (.bss)

// ---------------- PTX helpers (base sm_103 legal; NO tcgen05) ----------------
__device__ __forceinline__ uint32_t smem_u32(const void* p) {
    uint32_t a;
    asm("{ .reg .u64 t; cvta.to.shared.u64 t, %1; cvt.u32.u64 %0, t; }" : "=r"(a) : "l"(p));
    return a;
}
__device__ __forceinline__ void mbar_init(uint32_t mbar, uint32_t cnt) {
    asm volatile("mbarrier.init.shared.b64 [%0], %1;" :: "r"(mbar), "r"(cnt) : "memory");
}
__device__ __forceinline__ void mbar_expect_tx(uint32_t mbar, uint32_t bytes) {
    asm volatile("mbarrier.arrive.expect_tx.shared.b64 _, [%0], %1;"
                 :: "r"(mbar), "r"(bytes) : "memory");
}
__device__ __forceinline__ void mbar_arrive(uint32_t mbar) {
    asm volatile("mbarrier.arrive.shared.b64 _, [%0];" :: "r"(mbar) : "memory");
}
__device__ __forceinline__ void mbar_wait(uint32_t mbar, uint32_t parity) {
    asm volatile(
        "{\n\t.reg .pred P;\n\t"
        "WL_%=:\n\t"
        "mbarrier.try_wait.parity.acquire.cta.shared::cta.b64 P, [%0], %1, 0x989680;\n\t"
        "@P bra.uni WD_%=;\n\t"
        "bra.uni WL_%=;\n\t"
        "WD_%=:\n\t}"
        :: "r"(mbar), "r"(parity) : "memory");
}
__device__ __forceinline__ void bulk_g2s(uint32_t dst, const void* src, uint32_t bytes, uint32_t mbar) {
    asm volatile(
        "cp.async.bulk.shared::cluster.global.mbarrier::complete_tx::bytes [%0], [%1], %2, [%3];"
        :: "r"(dst), "l"(src), "r"(bytes), "r"(mbar) : "memory");
}
__device__ __forceinline__ void fence_async() {
    asm volatile("fence.proxy.async.shared::cta;" ::: "memory");
}
__device__ __forceinline__ void ldsm_x4(uint32_t* r, uint32_t addr) {
    asm volatile("ldmatrix.sync.aligned.m8n8.x4.shared.b16 {%0,%1,%2,%3}, [%4];"
                 : "=r"(r[0]), "=r"(r[1]), "=r"(r[2]), "=r"(r[3]) : "r"(addr));
}
__device__ __forceinline__ void mma16(float* d, const uint32_t* a, uint32_t b0, uint32_t b1) {
    asm volatile(
        "mma.sync.aligned.m16n8k16.row.col.f32.f16.f16.f32 "
        "{%0,%1,%2,%3}, {%4,%5,%6,%7}, {%8,%9}, {%0,%1,%2,%3};"
        : "+f"(d[0]), "+f"(d[1]), "+f"(d[2]), "+f"(d[3])
        : "r"(a[0]), "r"(a[1]), "r"(a[2]), "r"(a[3]), "r"(b0), "r"(b1));
}
// streaming store (evict-first) — protect W/X L2 residency from output stream
__device__ __forceinline__ void stcs(float* p, float v) {
    asm volatile("st.global.cs.f32 [%0], %1;" :: "l"(p), "f"(v) : "memory");
}

// ---------------- prologue: demod ----------------
__global__ void demod_kernel(const float* __restrict__ y, const float* __restrict__ w) {
    int o = blockIdx.x, b = blockIdx.y, ci = threadIdx.x;
    float m = 1.0f + y[b * CI + ci];
    const float* wr = w + ((size_t)o * CI + ci) * 5;
    float s = wr[0]*wr[0] + wr[1]*wr[1] + wr[2]*wr[2] + wr[3]*wr[3] + wr[4]*wr[4];
    float v = m * m * s;
#pragma unroll
    for (int off = 16; off; off >>= 1) v += __shfl_xor_sync(0xffffffffu, v, off);
    __shared__ float red[8];
    if ((threadIdx.x & 31) == 0) red[threadIdx.x >> 5] = v;
    __syncthreads();
    if (threadIdx.x == 0) {
        float t = red[0]+red[1]+red[2]+red[3]+red[4]+red[5]+red[6]+red[7];
        g_demod[b * CO + o] = rsqrtf(t + EPSV);
    }
}

// ---------------- prologue: x -> fp16, transpose, pad, k-half planes ----------------
__global__ __launch_bounds__(256) void prep_x_kernel(const float* __restrict__ x) {
    __shared__ float xs[16][132];
    const int t = threadIdx.x;
    const int h = blockIdx.x, ck = blockIdx.y, b = blockIdx.z;

    const float* src = x + ((size_t)(b * CI + ck * 16) * HH + h) * WW;
#pragma unroll
    for (int r = 0; r < 8; r++) {
        int idx = t + r * 256;
        int j = idx >> 7, pix = idx & 127;
        xs[j][pix] = src[(size_t)j * HH * WW + pix];
    }
    __syncthreads();

    __half2* dst = (__half2*)(g_xt + ((size_t)((b * CKN + ck) * HH + h)) * XROWH);
#pragma unroll
    for (int r = 0; r < 4; r++) {
        int o = t + r * 256;               // 0..1023: pix*8 + cpair p
        int pix = o >> 3, p = o & 7;
        int ci0 = p * 2;                   // plain k order
        int chalf = p >> 2, q = p & 3;
        dst[chalf * 520 + (pix + 1) * 4 + q] = __floats2half2_rn(xs[ci0][pix], xs[ci0 + 1][pix]);
    }
    if (t < 16) {   // zero borders: pix 0 and 129, both planes
        int side = t >> 3, p = t & 7;
        int chalf = p >> 2, q = p & 3;
        dst[chalf * 520 + (side ? 129 : 0) * 4 + q] = __floats2half2_rn(0.f, 0.f);
    }
}

// ---------------- prologue: weights -> [tap][khalf][co][8 halves] ----------
__global__ __launch_bounds__(128) void prep_w_kernel(
    const float* __restrict__ w, const float* __restrict__ y)
{
    const int ck = blockIdx.x, ct = blockIdx.y, b = blockIdx.z;
    const int co = threadIdx.x;
    const int o = ct * 128 + co;
    const float dd = g_demod[b * CO + o];
    __half2* blk = (__half2*)(g_weff + ((size_t)((b * 2 + ct) * CKN + ck)) * WH);
#pragma unroll
    for (int kh = 0; kh < 2; kh++) {
#pragma unroll
        for (int j2 = 0; j2 < 4; j2++) {
            const int ci0 = ck * 16 + kh * 8 + j2 * 2;
            const float m0 = (1.0f + y[b * CI + ci0]) * dd;
            const float m1 = (1.0f + y[b * CI + ci0 + 1]) * dd;
            const float* wp0 = w + ((size_t)o * CI + ci0) * 5;
            const float* wp1 = wp0 + 5;
#pragma unroll
            for (int tap = 0; tap < 5; tap++)
                blk[((tap * 2 + kh) * 128 + co) * 4 + j2] =
                    __floats2half2_rn(wp0[tap] * m0, wp1[tap] * m1);
        }
    }
}

// ---------------- producer: one chunk into a stage ----------------
__device__ __forceinline__ void issue_chunk(
    int c, int h0, int b, int ct, uint32_t stage_dst, uint32_t full_mb)
{
    mbar_expect_tx(full_mb, TXBYTES);
    const __half* xb = g_xt + ((size_t)(b * CKN + c) * HH) * XROWH;
    if (h0 >= 2 && h0 <= 124) {
        bulk_g2s(stage_dst, xb + (size_t)(h0 - 1) * XROWH, 4 * XROWH * 2, full_mb);
    } else if (h0 == 0) {
        bulk_g2s(stage_dst, g_zero, XROWH * 2, full_mb);
        bulk_g2s(stage_dst + XROWH * 2, xb, 3 * XROWH * 2, full_mb);
    } else { // h0 == 126
        bulk_g2s(stage_dst, xb + (size_t)125 * XROWH, 3 * XROWH * 2, full_mb);
        bulk_g2s(stage_dst + 3 * XROWH * 2, g_zero, XROWH * 2, full_mb);
    }
    bulk_g2s(stage_dst + XH * 2,
             g_weff + ((size_t)((b * 2 + ct) * CKN + c)) * WH, WH * 2, full_mb);
}

// ---------------- chunk body (rotated tap order for 4-way desync) ----------------
template <int START>
__device__ __forceinline__ void do_chunk(
    float (&d)[4][4][4], uint32_t xs_u, uint32_t ws_u, int row, int pbase)
{
#pragma unroll
    for (int ti = 0; ti < 5; ti++) {
        const int tap   = (START + ti) % 5;
        const int xrow  = row + ((tap == 0) ? 0 : (tap == 4 ? 2 : 1));
        const int shift = (tap == 1) ? -1 : ((tap == 3) ? 1 : 0);
        const uint32_t ub = xs_u + (uint32_t)(xrow * (XROWH * 2)
                          + (pbase + 1 + shift) * 16);
        uint32_t a[4][4];
#pragma unroll
        for (int f = 0; f < 4; f++)
            ldsm_x4(a[f], ub + (uint32_t)(f * 256));
        uint32_t bp0[4], bp1[4];
        ldsm_x4(bp0, ws_u + (uint32_t)(tap * 4096));
        ldsm_x4(bp1, ws_u + (uint32_t)(tap * 4096 + 256));
#pragma unroll
        for (int f = 0; f < 4; f++) {
            mma16(d[f][0], a[f], bp0[0], bp0[1]);
            mma16(d[f][1], a[f], bp0[2], bp0[3]);
            mma16(d[f][2], a[f], bp1[0], bp1[1]);
            mma16(d[f][3], a[f], bp1[2], bp1[3]);
        }
    }
}

// -- main: fp16 mma.sync, 16 compute warps (M64xN32, rotated) + producer warp ---------
__global__ __launch_bounds__(544, 1) void conv_mma_kernel(float* __restrict__ out) {
    extern __shared__ __half smem[];
    const uint32_t smem_base = smem_u32(smem);
    const uint32_t barbase = smem_base + NSTAGE * STAGEH * 2;

    const int tid  = threadIdx.x;
    const int lane = tid & 31;
    const int wid  = tid >> 5;
    const int grp  = lane >> 2;
    const int tig  = lane & 3;

    const int h0 = blockIdx.x * 2;
    const int ct = blockIdx.y;
    const int b  = blockIdx.z;

    if (tid == 0) {
        for (int s = 0; s < NSTAGE; s++) {
            mbar_init(barbase + s * 8, 1);                    // full
            mbar_init(barbase + NSTAGE * 8 + s * 8, 16);      // empty (per compute warp)
        }
        fence_async();
    }
    __syncthreads();

    if (wid == 16) {
        // ---------- dedicated producer warp ----------
        if (lane == 0) {
            for (int cc = 0; cc < CKN; cc++) {
                const int s = cc % NSTAGE;
                if (cc >= NSTAGE) {
                    const int r = (cc - NSTAGE) / NSTAGE;
                    mbar_wait(barbase + NSTAGE * 8 + s * 8, r & 1);
                }
                issue_chunk(cc, h0, b, ct, smem_base + s * STAGEH * 2, barbase + s * 8);
            }
        }
        return;
    }

    // ---------- compute warps: M64 x N32 ----------
    const int mg = wid >> 2;             // 0..3 : M64 tile over M=256
    const int ng = wid & 3;              // 0..3 : N32 tile over N=128
    const int row = mg >> 1;             // output row within CTA (0/1)
    const int pbase = (mg & 1) * 64;     // pixel base

    const uint32_t loff = (uint32_t)((lane & 15) * 16 + (lane >> 4) * XPLANEB);
    const uint32_t wloff = (uint32_t)((lane & 7) * 16 + ((lane >> 3) & 1) * 2048
                         + (lane >> 4) * 128);

    float d[4][4][4];
#pragma unroll
    for (int f = 0; f < 4; f++)
#pragma unroll
        for (int nf = 0; nf < 4; nf++)
#pragma unroll
            for (int k = 0; k < 4; k++) d[f][nf][k] = 0.0f;

    for (int c = 0; c < CKN; c++) {
        const int s = c % NSTAGE;
        const int r = c / NSTAGE;
        mbar_wait(barbase + s * 8, r & 1);
        const uint32_t xs_u = smem_base + s * STAGEH * 2 + loff;
        const uint32_t ws_u = smem_base + s * STAGEH * 2 + XH * 2
                            + (uint32_t)(ng * 512) + wloff;

        switch (mg) {
            case 0: do_chunk<0>(d, xs_u, ws_u, row, pbase); break;
            case 1: do_chunk<1>(d, xs_u, ws_u, row, pbase); break;
            case 2: do_chunk<2>(d, xs_u, ws_u, row, pbase); break;
            default: do_chunk<3>(d, xs_u, ws_u, row, pbase); break;
        }

        if (lane == 0) mbar_arrive(barbase + NSTAGE * 8 + s * 8);
    }

    // ---- epilogue: demod folded into weights -> streaming stores ----
    float* ob = out + (((size_t)b * CO + ct * 128) * HH + (h0 + row)) * WW;
#pragma unroll
    for (int f = 0; f < 4; f++) {
        const int p = pbase + f * 16 + grp;
#pragma unroll
        for (int nf = 0; nf < 4; nf++) {
            const int co = ng * 32 + nf * 8 + tig * 2;
            stcs(ob + (size_t)co * (HH * WW) + p,           d[f][nf][0]);
            stcs(ob + (size_t)(co + 1) * (HH * WW) + p,     d[f][nf][1]);
            stcs(ob + (size_t)co * (HH * WW) + p + 8,       d[f][nf][2]);
            stcs(ob + (size_t)(co + 1) * (HH * WW) + p + 8, d[f][nf][3]);
        }
    }
}

extern "C" void kernel_launch(void* const* d_in, const int* in_sizes, int n_in,
                              void* d_out, int out_size) {
    const float* x = (const float*)d_in[0];
    const float* y = (const float*)d_in[1];
    const float* w = (const float*)d_in[2];
    float* out = (float*)d_out;

    cudaFuncSetAttribute(conv_mma_kernel, cudaFuncAttributeMaxDynamicSharedMemorySize, SMEM_DYN);

    demod_kernel<<<dim3(CO, BS), 256>>>(y, w);
    prep_x_kernel<<<dim3(HH, CKN, BS), 256>>>(x);
    prep_w_kernel<<<dim3(CKN, 2, BS), 128>>>(w, y);
    conv_mma_kernel<<<dim3(HH / 2, 2, BS), 544, SMEM_DYN>>>(out);
}